// round 2
// baseline (speedup 1.0000x reference)
#include <cuda_runtime.h>
#include <cuda_bf16.h>

#define BB 128   // batch (docs)
#define NN 50    // entities per doc
#define KK 20    // neighbors
#define DD 128   // embedding dim
#define NK (NN*KK)          // 1000
#define TOT (BB*NN*KK)      // 128000

// scratch: logits, then overwritten in-place with attention weights
__device__ float g_att[TOT];

// ---------------------------------------------------------------------------
// Kernel 1: logits[b,n,k] = relu( dot(concat(ee, ne, nr), W_att) + b_att )
// one warp per (b,n,k); float4 vectorized row loads (lane covers 4 floats)
// ---------------------------------------------------------------------------
__global__ __launch_bounds__(256) void k_logits(
    const int* __restrict__ entity_ids,
    const int* __restrict__ adj_entity,
    const int* __restrict__ adj_relation,
    const float* __restrict__ ent_emb,
    const float* __restrict__ rel_emb,
    const float* __restrict__ W_att,
    const float* __restrict__ b_att)
{
    int warp = (blockIdx.x * blockDim.x + threadIdx.x) >> 5;
    if (warp >= TOT) return;
    int lane = threadIdx.x & 31;

    int b   = warp / NK;
    int rem = warp - b * NK;
    int n   = rem / KK;
    int k   = rem - n * KK;

    int eid = entity_ids[b * NN + n];
    int nid = adj_entity[eid * KK + k];
    int rid = adj_relation[eid * KK + k];

    const float4* e4 = (const float4*)(ent_emb + (size_t)eid * DD);
    const float4* n4 = (const float4*)(ent_emb + (size_t)nid * DD);
    const float4* r4 = (const float4*)(rel_emb + (size_t)rid * DD);
    const float4* w0 = (const float4*)(W_att);
    const float4* w1 = (const float4*)(W_att + DD);
    const float4* w2 = (const float4*)(W_att + 2 * DD);

    float4 a  = e4[lane], bb = n4[lane], c  = r4[lane];
    float4 wa = w0[lane], wb = w1[lane], wc = w2[lane];

    float s = a.x*wa.x + a.y*wa.y + a.z*wa.z + a.w*wa.w
            + bb.x*wb.x + bb.y*wb.y + bb.z*wb.z + bb.w*wb.w
            + c.x*wc.x + c.y*wc.y + c.z*wc.z + c.w*wc.w;

    #pragma unroll
    for (int off = 16; off > 0; off >>= 1)
        s += __shfl_xor_sync(0xffffffffu, s, off);

    if (lane == 0)
        g_att[warp] = fmaxf(s + b_att[0], 0.0f);
}

// ---------------------------------------------------------------------------
// Kernel 2: softmax over the batch axis (axis 0) for each (n,k).
// one block per (n,k), 128 threads = b index. Overwrites g_att in place.
// ---------------------------------------------------------------------------
__global__ __launch_bounds__(128) void k_softmax()
{
    int nk = blockIdx.x;           // 0..NK-1
    int b  = threadIdx.x;          // 0..127
    int lane = b & 31, wid = b >> 5;
    __shared__ float red[4];

    float v = g_att[b * NK + nk];

    // max over block
    float m = v;
    #pragma unroll
    for (int off = 16; off > 0; off >>= 1)
        m = fmaxf(m, __shfl_xor_sync(0xffffffffu, m, off));
    if (lane == 0) red[wid] = m;
    __syncthreads();
    m = fmaxf(fmaxf(red[0], red[1]), fmaxf(red[2], red[3]));

    float e = __expf(v - m);

    // sum over block
    float s = e;
    #pragma unroll
    for (int off = 16; off > 0; off >>= 1)
        s += __shfl_xor_sync(0xffffffffu, s, off);
    __syncthreads();               // red[] reuse
    if (lane == 0) red[wid] = s;
    __syncthreads();
    s = red[0] + red[1] + red[2] + red[3];

    g_att[b * NK + nk] = e / s;
}

// ---------------------------------------------------------------------------
// Kernel 3: neighbor_att[b,n,:] = sum_k att * ne ; out = relu([ee,nb]@W_conv+b)
// one block per (b,n), 128 threads = output dim d.
// ---------------------------------------------------------------------------
__global__ __launch_bounds__(128) void k_aggregate(
    const int* __restrict__ entity_ids,
    const int* __restrict__ adj_entity,
    const float* __restrict__ ent_emb,
    const float* __restrict__ W_conv,
    const float* __restrict__ b_conv,
    float* __restrict__ out)
{
    __shared__ float s_agg[2 * DD];
    __shared__ int   s_nid[KK];
    __shared__ float s_att[KK];

    int bn = blockIdx.x;           // b*NN + n
    int b  = bn / NN;
    int n  = bn - b * NN;
    int d  = threadIdx.x;

    int eid = entity_ids[bn];

    if (d < KK) {
        s_nid[d] = adj_entity[eid * KK + d];
        s_att[d] = g_att[b * NK + n * KK + d];
    }
    s_agg[d] = ent_emb[(size_t)eid * DD + d];
    __syncthreads();

    // weighted neighbor sum: 20 independent coalesced row gathers
    float nb = 0.0f;
    #pragma unroll
    for (int k = 0; k < KK; k++)
        nb = fmaf(s_att[k], ent_emb[(size_t)s_nid[k] * DD + d], nb);
    s_agg[DD + d] = nb;
    __syncthreads();

    // matvec against W_conv column d (coalesced across threads, L1-resident)
    float acc = b_conv[d];
    #pragma unroll 8
    for (int j = 0; j < 2 * DD; j++)
        acc = fmaf(s_agg[j], W_conv[j * DD + d], acc);

    out[bn * DD + d] = fmaxf(acc, 0.0f);
}

// ---------------------------------------------------------------------------
extern "C" void kernel_launch(void* const* d_in, const int* in_sizes, int n_in,
                              void* d_out, int out_size)
{
    const int*   entity_ids = (const int*)  d_in[0];
    const int*   adj_entity = (const int*)  d_in[1];
    const int*   adj_rel    = (const int*)  d_in[2];
    const float* ent_emb    = (const float*)d_in[3];
    const float* rel_emb    = (const float*)d_in[4];
    const float* W_att      = (const float*)d_in[5];
    const float* b_att      = (const float*)d_in[6];
    const float* W_conv     = (const float*)d_in[7];
    const float* b_conv     = (const float*)d_in[8];
    float* out = (float*)d_out;

    // kernel 1: one warp per (b,n,k) -> TOT warps, 8 warps/block
    int blocks1 = (TOT * 32 + 255) / 256;
    k_logits<<<blocks1, 256>>>(entity_ids, adj_entity, adj_rel,
                               ent_emb, rel_emb, W_att, b_att);

    // kernel 2: one block per (n,k)
    k_softmax<<<NK, 128>>>();

    // kernel 3: one block per (b,n)
    k_aggregate<<<BB * NN, 128>>>(entity_ids, adj_entity, ent_emb,
                                  W_conv, b_conv, out);
}

// round 3
// speedup vs baseline: 1.3699x; 1.3699x over previous
#include <cuda_runtime.h>
#include <cuda_bf16.h>

#define BB 128   // batch
#define NN 50    // entities per doc
#define KK 20    // neighbors
#define DD 128   // embedding dim
#define NK (NN*KK)          // 1000
#define BN (BB*NN)          // 6400
#define TOT (BB*NN*KK)      // 128000

// scratch (transposed layout: att[nk][b])
__device__ float g_att[TOT];
__device__ float g_ee_dot[BN];
__device__ float g_rel_dot[128];   // R=100, padded

// ---- packed f32x2 helpers (sm_103a) --------------------------------------
__device__ __forceinline__ unsigned long long pack2(float lo, float hi) {
    unsigned long long r;
    asm("mov.b64 %0, {%1, %2};" : "=l"(r) : "f"(lo), "f"(hi));
    return r;
}
__device__ __forceinline__ void unpack2(unsigned long long v, float& lo, float& hi) {
    asm("mov.b64 {%0, %1}, %2;" : "=f"(lo), "=f"(hi) : "l"(v));
}
__device__ __forceinline__ unsigned long long fma2(unsigned long long a,
                                                   unsigned long long b,
                                                   unsigned long long c) {
    unsigned long long d;
    asm("fma.rn.f32x2 %0, %1, %2, %3;" : "=l"(d) : "l"(a), "l"(b), "l"(c));
    return d;
}

// ---------------------------------------------------------------------------
// Kernel A: precompute rel_dot[r] = dot(rel_emb[r], w2)  (100 warps)
//           and      ee_dot[bn]  = dot(ee, w0)           (6400 warps)
// ---------------------------------------------------------------------------
__global__ __launch_bounds__(256) void k_pre(
    const int* __restrict__ entity_ids,
    const float* __restrict__ ent_emb,
    const float* __restrict__ rel_emb,
    const float* __restrict__ W_att)
{
    int warp = (blockIdx.x * blockDim.x + threadIdx.x) >> 5;
    int lane = threadIdx.x & 31;
    if (warp >= BN + 100) return;

    const float4* row;
    const float4* w;
    if (warp < BN) {
        int eid = entity_ids[warp];
        row = (const float4*)(ent_emb + (size_t)eid * DD);
        w   = (const float4*)(W_att);            // w0
    } else {
        int r = warp - BN;
        row = (const float4*)(rel_emb + (size_t)r * DD);
        w   = (const float4*)(W_att + 2 * DD);   // w2
    }
    float4 a = row[lane], wv = w[lane];
    float s = a.x*wv.x + a.y*wv.y + a.z*wv.z + a.w*wv.w;
    #pragma unroll
    for (int off = 16; off > 0; off >>= 1)
        s += __shfl_xor_sync(0xffffffffu, s, off);
    if (lane == 0) {
        if (warp < BN) g_ee_dot[warp] = s;
        else           g_rel_dot[warp - BN] = s;
    }
}

// ---------------------------------------------------------------------------
// Kernel B: logits[b,n,k] = relu(ee_dot + dot(ne,w1) + rel_dot[rid] + b_att)
// one warp per (b,n,k); stores transposed: g_att[(n*KK+k)*BB + b]
// ---------------------------------------------------------------------------
__global__ __launch_bounds__(256) void k_logits(
    const int* __restrict__ entity_ids,
    const int* __restrict__ adj_entity,
    const int* __restrict__ adj_relation,
    const float* __restrict__ ent_emb,
    const float* __restrict__ W_att,
    const float* __restrict__ b_att)
{
    int warp = (blockIdx.x * blockDim.x + threadIdx.x) >> 5;
    int lane = threadIdx.x & 31;

    int b   = warp / NK;
    int rem = warp - b * NK;         // n*KK + k
    int bn  = b * NN + rem / KK;

    int eid = entity_ids[bn];
    int nid = adj_entity[eid * KK + (rem % KK)];
    int rid = adj_relation[eid * KK + (rem % KK)];

    const float4* n4 = (const float4*)(ent_emb + (size_t)nid * DD);
    const float4* w1 = (const float4*)(W_att + DD);

    float4 a = n4[lane], wv = w1[lane];
    float s = a.x*wv.x + a.y*wv.y + a.z*wv.z + a.w*wv.w;
    #pragma unroll
    for (int off = 16; off > 0; off >>= 1)
        s += __shfl_xor_sync(0xffffffffu, s, off);

    if (lane == 0) {
        float v = s + g_ee_dot[bn] + g_rel_dot[rid] + b_att[0];
        g_att[rem * BB + b] = fmaxf(v, 0.0f);
    }
}

// ---------------------------------------------------------------------------
// Kernel C: softmax over batch axis; block per (n,k); coalesced reads.
// ---------------------------------------------------------------------------
__global__ __launch_bounds__(128) void k_softmax()
{
    int nk = blockIdx.x;
    int b  = threadIdx.x;
    int lane = b & 31, wid = b >> 5;
    __shared__ float red[4];

    float v = g_att[nk * BB + b];

    float m = v;
    #pragma unroll
    for (int off = 16; off > 0; off >>= 1)
        m = fmaxf(m, __shfl_xor_sync(0xffffffffu, m, off));
    if (lane == 0) red[wid] = m;
    __syncthreads();
    m = fmaxf(fmaxf(red[0], red[1]), fmaxf(red[2], red[3]));

    float e = __expf(v - m);
    float s = e;
    #pragma unroll
    for (int off = 16; off > 0; off >>= 1)
        s += __shfl_xor_sync(0xffffffffu, s, off);
    __syncthreads();
    if (lane == 0) red[wid] = s;
    __syncthreads();
    s = red[0] + red[1] + red[2] + red[3];

    g_att[nk * BB + b] = e / s;
}

// ---------------------------------------------------------------------------
// Kernel D: 16 (b,n) rows per block, 128 threads.
// Phase 1 (4 warps, 4 rows each): gather ee + weighted neighbor sum into
//   transposed shared s_aggT[j][row], j in [0,256).
// Phase 2: thread t -> outputs d0=2*(t&63), rows rg*8..rg*8+7 (rg=t>>6);
//   register-tiled matvec with packed f32x2 FMA.
// ---------------------------------------------------------------------------
#define ROWS 16
#define PAD  20          // row pitch in floats (16B-aligned: 20*4=80, 80j%16==0)

__global__ __launch_bounds__(128) void k_aggregate(
    const int* __restrict__ entity_ids,
    const int* __restrict__ adj_entity,
    const float* __restrict__ ent_emb,
    const float* __restrict__ W_conv,
    const float* __restrict__ b_conv,
    float* __restrict__ out)
{
    __shared__ float sT[2 * DD * PAD];   // [256][PAD], use first ROWS cols

    int lane = threadIdx.x & 31;
    int warp = threadIdx.x >> 5;         // 0..3
    int bn0  = blockIdx.x * ROWS;

    // ---- phase 1: gather ----
    for (int m = 0; m < 4; m++) {
        int bnl = warp * 4 + m;
        int bn  = bn0 + bnl;
        int b   = bn / NN;
        int n   = bn - b * NN;
        int eid = entity_ids[bn];

        int   my_nid = 0;
        float my_att = 0.0f;
        if (lane < KK) {
            my_nid = adj_entity[eid * KK + lane];
            my_att = g_att[(n * KK + lane) * BB + b];
        }

        float ee[4], nb[4];
        #pragma unroll
        for (int i = 0; i < 4; i++) {
            ee[i] = ent_emb[(size_t)eid * DD + lane + 32 * i];
            nb[i] = 0.0f;
        }
        #pragma unroll
        for (int k = 0; k < KK; k++) {
            int   nid = __shfl_sync(0xffffffffu, my_nid, k);
            float at  = __shfl_sync(0xffffffffu, my_att, k);
            const float* row = ent_emb + (size_t)nid * DD;
            #pragma unroll
            for (int i = 0; i < 4; i++)
                nb[i] = fmaf(at, row[lane + 32 * i], nb[i]);
        }
        #pragma unroll
        for (int i = 0; i < 4; i++) {
            sT[(lane + 32 * i) * PAD + bnl]      = ee[i];
            sT[(DD + lane + 32 * i) * PAD + bnl] = nb[i];
        }
    }
    __syncthreads();

    // ---- phase 2: matvec with f32x2 ----
    int p  = threadIdx.x & 63;   // output pair index
    int d0 = 2 * p;
    int rg = threadIdx.x >> 6;   // row group 0/1 -> rows rg*8..rg*8+7

    unsigned long long acc[8];
    {
        unsigned long long init = pack2(b_conv[d0], b_conv[d0 + 1]);
        #pragma unroll
        for (int r = 0; r < 8; r++) acc[r] = init;
    }

    const float* sbase = sT + rg * 8;
    #pragma unroll 4
    for (int j = 0; j < 2 * DD; j++) {
        float2 w2 = *(const float2*)(W_conv + j * DD + d0);
        unsigned long long w = pack2(w2.x, w2.y);
        float4 sa = *(const float4*)(sbase + j * PAD);
        float4 sb = *(const float4*)(sbase + j * PAD + 4);
        acc[0] = fma2(pack2(sa.x, sa.x), w, acc[0]);
        acc[1] = fma2(pack2(sa.y, sa.y), w, acc[1]);
        acc[2] = fma2(pack2(sa.z, sa.z), w, acc[2]);
        acc[3] = fma2(pack2(sa.w, sa.w), w, acc[3]);
        acc[4] = fma2(pack2(sb.x, sb.x), w, acc[4]);
        acc[5] = fma2(pack2(sb.y, sb.y), w, acc[5]);
        acc[6] = fma2(pack2(sb.z, sb.z), w, acc[6]);
        acc[7] = fma2(pack2(sb.w, sb.w), w, acc[7]);
    }

    #pragma unroll
    for (int r = 0; r < 8; r++) {
        float lo, hi;
        unpack2(acc[r], lo, hi);
        int bn = bn0 + rg * 8 + r;
        float2 o = make_float2(fmaxf(lo, 0.0f), fmaxf(hi, 0.0f));
        *(float2*)(out + (size_t)bn * DD + d0) = o;
    }
}

// ---------------------------------------------------------------------------
extern "C" void kernel_launch(void* const* d_in, const int* in_sizes, int n_in,
                              void* d_out, int out_size)
{
    const int*   entity_ids = (const int*)  d_in[0];
    const int*   adj_entity = (const int*)  d_in[1];
    const int*   adj_rel    = (const int*)  d_in[2];
    const float* ent_emb    = (const float*)d_in[3];
    const float* rel_emb    = (const float*)d_in[4];
    const float* W_att      = (const float*)d_in[5];
    const float* b_att      = (const float*)d_in[6];
    const float* W_conv     = (const float*)d_in[7];
    const float* b_conv     = (const float*)d_in[8];
    float* out = (float*)d_out;

    // A: 6500 warps
    k_pre<<<(BN + 100 + 7) / 8, 256>>>(entity_ids, ent_emb, rel_emb, W_att);

    // B: 128000 warps (exactly 16000 blocks of 8 warps)
    k_logits<<<TOT / 8, 256>>>(entity_ids, adj_entity, adj_rel,
                               ent_emb, W_att, b_att);

    // C: one block per (n,k)
    k_softmax<<<NK, 128>>>();

    // D: 16 (b,n) rows per block
    k_aggregate<<<BN / ROWS, 128>>>(entity_ids, adj_entity, ent_emb,
                                    W_conv, b_conv, out);
}